// round 3
// baseline (speedup 1.0000x reference)
#include <cuda_runtime.h>
#include <cuda_fp16.h>

#define BNUM 8
#define NPTS 30000
#define TOTALP (BNUM * NPTS)
#define OUTC 963            // 3 + 64 + 128 + 256 + 512
#define SGRID 64            // spatial bins per axis
#define NBINS (BNUM * SGRID * SGRID)  // 32768

// NHWC fp16 scratch for the 4 feature pyramids
__device__ __half g_f0[(size_t)BNUM * 128 * 128 * 64];
__device__ __half g_f1[(size_t)BNUM * 64 * 64 * 128];
__device__ __half g_f2[(size_t)BNUM * 32 * 32 * 256];
__device__ __half g_f3[(size_t)BNUM * 16 * 16 * 512];

// Sorting scratch
__device__ int    g_hist[NBINS];
__device__ int    g_cursor[NBINS];
__device__ int    g_binid[TOTALP];
__device__ int    g_perm[TOTALP];
__device__ float2 g_proj[TOTALP];

// ---------------------------------------------------------------------------
// NCHW fp32 -> NHWC fp16 transpose
// ---------------------------------------------------------------------------
__global__ void transpose_nchw_nhwc_h(const float* __restrict__ in,
                                      __half* __restrict__ out,
                                      int C, int HW) {
    __shared__ float tile[32][33];
    int b = blockIdx.z;
    const float* src = in + (size_t)b * C * HW;
    __half* dst = out + (size_t)b * C * HW;
    int hw0 = blockIdx.x * 32;
    int c0  = blockIdx.y * 32;

#pragma unroll
    for (int k = 0; k < 4; k++) {
        int c = c0 + threadIdx.y + k * 8;
        tile[threadIdx.y + k * 8][threadIdx.x] =
            src[(size_t)c * HW + hw0 + threadIdx.x];
    }
    __syncthreads();
#pragma unroll
    for (int k = 0; k < 4; k++) {
        int hw = hw0 + threadIdx.y + k * 8;
        dst[(size_t)hw * C + c0 + threadIdx.x] =
            __float2half(tile[threadIdx.x][threadIdx.y + k * 8]);
    }
}

// ---------------------------------------------------------------------------
// Projection + binning: one thread per point.
// ---------------------------------------------------------------------------
__global__ void proj_bin_kernel(const float* __restrict__ resolution,
                                const float* __restrict__ inputs,
                                const float* __restrict__ camK) {
    int pid = blockIdx.x * blockDim.x + threadIdx.x;
    if (pid >= TOTALP) return;
    int b = pid / NPTS;

    const float cam_scale = 256.0f / 1920.0f;
    float hr0 = (resolution[0] - 1.0f) * 0.5f;
    float hr1 = (resolution[1] - 1.0f) * 0.5f;

    const float* K = camK + b * 9;
    float K00 = K[0] * cam_scale;
    float K01 = K[1] * cam_scale;
    float K02 = K[2] * cam_scale;
    float K11 = K[4] * cam_scale;
    float K12 = K[5] * cam_scale;

    const float* p = inputs + (size_t)pid * 3;
    float X = p[0];
    float Y = p[1];
    float Z = p[2] - 0.8f;

    float w = (-K00 * X - K01 * Y) / Z + K02 - hr0;
    float h = K11 * (Y / Z) + K12 - hr1;
    float wn = fminf(fmaxf(w / hr0, -1.0f), 1.0f);
    float hn = fminf(fmaxf(h / hr1, -1.0f), 1.0f);

    g_proj[pid] = make_float2(wn, hn);

    int ix = min((int)((wn + 1.0f) * (SGRID * 0.5f)), SGRID - 1);
    int iy = min((int)((hn + 1.0f) * (SGRID * 0.5f)), SGRID - 1);
    int bin = (b * SGRID + iy) * SGRID + ix;
    g_binid[pid] = bin;
    atomicAdd(&g_hist[bin], 1);
}

// ---------------------------------------------------------------------------
// Exclusive scan over NBINS (single block, 1024 threads, 32 elems/thread)
// ---------------------------------------------------------------------------
__global__ void scan_kernel() {
    __shared__ int warp_sums[32];
    int t = threadIdx.x;
    int lane = t & 31, wid = t >> 5;
    const int EPT = NBINS / 1024;
    int base = t * EPT;
    int vals[EPT];
    int s = 0;
#pragma unroll
    for (int i = 0; i < EPT; i++) { vals[i] = g_hist[base + i]; s += vals[i]; }

    int x = s;
#pragma unroll
    for (int off = 1; off < 32; off <<= 1) {
        int y = __shfl_up_sync(0xffffffffu, x, off);
        if (lane >= off) x += y;
    }
    if (lane == 31) warp_sums[wid] = x;
    __syncthreads();
    if (wid == 0) {
        int y = warp_sums[lane];
#pragma unroll
        for (int off = 1; off < 32; off <<= 1) {
            int z = __shfl_up_sync(0xffffffffu, y, off);
            if (lane >= off) y += z;
        }
        warp_sums[lane] = y;
    }
    __syncthreads();
    int excl = x - s + (wid > 0 ? warp_sums[wid - 1] : 0);
    int run = excl;
#pragma unroll
    for (int i = 0; i < EPT; i++) { g_cursor[base + i] = run; run += vals[i]; }
}

// ---------------------------------------------------------------------------
// Scatter: build permutation
// ---------------------------------------------------------------------------
__global__ void scatter_kernel() {
    int pid = blockIdx.x * blockDim.x + threadIdx.x;
    if (pid >= TOTALP) return;
    int pos = atomicAdd(&g_cursor[g_binid[pid]], 1);
    g_perm[pos] = pid;
}

// ---------------------------------------------------------------------------
// Gather helpers (fp16 NHWC)
// ---------------------------------------------------------------------------
__device__ __forceinline__ void acc4(const __half* __restrict__ p, float w,
                                     float& r0, float& r1, float& r2, float& r3) {
    uint2 v = *(const uint2*)p;
    __half2 h0 = *reinterpret_cast<const __half2*>(&v.x);
    __half2 h1 = *reinterpret_cast<const __half2*>(&v.y);
    float2 f0 = __half22float2(h0);
    float2 f1 = __half22float2(h1);
    r0 = fmaf(f0.x, w, r0);
    r1 = fmaf(f0.y, w, r1);
    r2 = fmaf(f1.x, w, r2);
    r3 = fmaf(f1.y, w, r3);
}

template <int C, int H, int W, int OFF>
__device__ __forceinline__ void sample_level(const __half* __restrict__ g,
                                             int b, int lane,
                                             float wn, float hn,
                                             float* __restrict__ orow) {
    float x = ((wn + 1.0f) * (float)W - 1.0f) * 0.5f;
    float y = ((hn + 1.0f) * (float)H - 1.0f) * 0.5f;
    float fx0 = floorf(x), fy0 = floorf(y);
    float tx = x - fx0, ty = y - fy0;
    int x0 = (int)fx0, y0 = (int)fy0;
    int x1 = x0 + 1,   y1 = y0 + 1;

    float wx0 = 1.0f - tx, wx1 = tx;
    float wy0 = 1.0f - ty, wy1 = ty;

    bool vx0 = (x0 >= 0) && (x0 < W);
    bool vx1 = (x1 >= 0) && (x1 < W);
    bool vy0 = (y0 >= 0) && (y0 < H);
    bool vy1 = (y1 >= 0) && (y1 < H);

    float w00 = (vx0 && vy0) ? wx0 * wy0 : 0.0f;
    float w10 = (vx1 && vy0) ? wx1 * wy0 : 0.0f;
    float w01 = (vx0 && vy1) ? wx0 * wy1 : 0.0f;
    float w11 = (vx1 && vy1) ? wx1 * wy1 : 0.0f;

    int x0c = min(max(x0, 0), W - 1), x1c = min(max(x1, 0), W - 1);
    int y0c = min(max(y0, 0), H - 1), y1c = min(max(y1, 0), H - 1);

    const __half* row0 = g + ((size_t)(b * H + y0c) * W) * C;
    const __half* row1 = g + ((size_t)(b * H + y1c) * W) * C;
    const __half* p00 = row0 + (size_t)x0c * C;
    const __half* p10 = row0 + (size_t)x1c * C;
    const __half* p01 = row1 + (size_t)x0c * C;
    const __half* p11 = row1 + (size_t)x1c * C;

#pragma unroll
    for (int c = lane * 4; c < C; c += 128) {
        float r0 = 0.f, r1 = 0.f, r2 = 0.f, r3 = 0.f;
        acc4(p00 + c, w00, r0, r1, r2, r3);
        acc4(p10 + c, w10, r0, r1, r2, r3);
        acc4(p01 + c, w01, r0, r1, r2, r3);
        acc4(p11 + c, w11, r0, r1, r2, r3);
        float* o = orow + OFF + c;
        o[0] = r0; o[1] = r1; o[2] = r2; o[3] = r3;
    }
}

// ---------------------------------------------------------------------------
// Main gather kernel: 1 warp per permuted point slot, 32 warps per block
// (block ~ one spatial bin => high L1 line reuse on corner reads).
// ---------------------------------------------------------------------------
__global__ void __launch_bounds__(1024)
gather_kernel(const float* __restrict__ inputs,
              float* __restrict__ out) {
    int slot = (blockIdx.x * blockDim.x + threadIdx.x) >> 5;
    int lane = threadIdx.x & 31;
    if (slot >= TOTALP) return;

    int pid = g_perm[slot];
    int b = pid / NPTS;

    float2 pr = g_proj[pid];
    float wn = pr.x, hn = pr.y;

    const float* p = inputs + (size_t)pid * 3;
    float* orow = out + (size_t)pid * OUTC;
    if (lane < 3) orow[lane] = p[lane];

    sample_level<64, 128, 128, 3>(g_f0, b, lane, wn, hn, orow);
    sample_level<128, 64, 64, 67>(g_f1, b, lane, wn, hn, orow);
    sample_level<256, 32, 32, 195>(g_f2, b, lane, wn, hn, orow);
    sample_level<512, 16, 16, 451>(g_f3, b, lane, wn, hn, orow);
}

extern "C" void kernel_launch(void* const* d_in, const int* in_sizes, int n_in,
                              void* d_out, int out_size) {
    const float* resolution = (const float*)d_in[0];
    const float* feat0 = (const float*)d_in[1];
    const float* feat1 = (const float*)d_in[2];
    const float* feat2 = (const float*)d_in[3];
    const float* feat3 = (const float*)d_in[4];
    const float* inputs = (const float*)d_in[5];
    const float* camK = (const float*)d_in[6];
    float* out = (float*)d_out;

    __half *pf0, *pf1, *pf2, *pf3;
    cudaGetSymbolAddress((void**)&pf0, g_f0);
    cudaGetSymbolAddress((void**)&pf1, g_f1);
    cudaGetSymbolAddress((void**)&pf2, g_f2);
    cudaGetSymbolAddress((void**)&pf3, g_f3);
    void* phist;
    cudaGetSymbolAddress(&phist, g_hist);

    dim3 tb(32, 8);
    transpose_nchw_nhwc_h<<<dim3(128 * 128 / 32, 64 / 32, BNUM), tb>>>(feat0, pf0, 64, 128 * 128);
    transpose_nchw_nhwc_h<<<dim3(64 * 64 / 32, 128 / 32, BNUM), tb>>>(feat1, pf1, 128, 64 * 64);
    transpose_nchw_nhwc_h<<<dim3(32 * 32 / 32, 256 / 32, BNUM), tb>>>(feat2, pf2, 256, 32 * 32);
    transpose_nchw_nhwc_h<<<dim3(16 * 16 / 32, 512 / 32, BNUM), tb>>>(feat3, pf3, 512, 16 * 16);

    cudaMemsetAsync(phist, 0, NBINS * sizeof(int));
    proj_bin_kernel<<<(TOTALP + 255) / 256, 256>>>(resolution, inputs, camK);
    scan_kernel<<<1, 1024>>>();
    scatter_kernel<<<(TOTALP + 255) / 256, 256>>>();

    const int WARPS_PER_BLOCK = 32;  // 1024 threads
    int nblocks = (TOTALP + WARPS_PER_BLOCK - 1) / WARPS_PER_BLOCK;
    gather_kernel<<<nblocks, WARPS_PER_BLOCK * 32>>>(inputs, out);
}

// round 4
// speedup vs baseline: 1.3814x; 1.3814x over previous
#include <cuda_runtime.h>
#include <cuda_fp16.h>

#define BNUM 8
#define NPTS 30000
#define TOTALP (BNUM * NPTS)
#define OUTC 963            // 3 + 64 + 128 + 256 + 512
#define SGRID 64            // spatial bins per axis
#define NBINS (BNUM * SGRID * SGRID)  // 32768

// NHWC fp16 scratch for the 4 feature pyramids
__device__ __half g_f0[(size_t)BNUM * 128 * 128 * 64];
__device__ __half g_f1[(size_t)BNUM * 64 * 64 * 128];
__device__ __half g_f2[(size_t)BNUM * 32 * 32 * 256];
__device__ __half g_f3[(size_t)BNUM * 16 * 16 * 512];

// Sorting scratch
__device__ int    g_hist[NBINS];
__device__ int    g_cursor[NBINS];
__device__ int    g_binid[TOTALP];
__device__ int    g_perm[TOTALP];
__device__ float2 g_proj[TOTALP];

// ---------------------------------------------------------------------------
// NCHW fp32 -> NHWC fp16 transpose
// ---------------------------------------------------------------------------
__global__ void transpose_nchw_nhwc_h(const float* __restrict__ in,
                                      __half* __restrict__ out,
                                      int C, int HW) {
    __shared__ float tile[32][33];
    int b = blockIdx.z;
    const float* src = in + (size_t)b * C * HW;
    __half* dst = out + (size_t)b * C * HW;
    int hw0 = blockIdx.x * 32;
    int c0  = blockIdx.y * 32;

#pragma unroll
    for (int k = 0; k < 4; k++) {
        int c = c0 + threadIdx.y + k * 8;
        tile[threadIdx.y + k * 8][threadIdx.x] =
            src[(size_t)c * HW + hw0 + threadIdx.x];
    }
    __syncthreads();
#pragma unroll
    for (int k = 0; k < 4; k++) {
        int hw = hw0 + threadIdx.y + k * 8;
        dst[(size_t)hw * C + c0 + threadIdx.x] =
            __float2half(tile[threadIdx.x][threadIdx.y + k * 8]);
    }
}

// ---------------------------------------------------------------------------
// Projection + binning: one thread per point.
// ---------------------------------------------------------------------------
__global__ void proj_bin_kernel(const float* __restrict__ resolution,
                                const float* __restrict__ inputs,
                                const float* __restrict__ camK) {
    int pid = blockIdx.x * blockDim.x + threadIdx.x;
    if (pid >= TOTALP) return;
    int b = pid / NPTS;

    const float cam_scale = 256.0f / 1920.0f;
    float hr0 = (resolution[0] - 1.0f) * 0.5f;
    float hr1 = (resolution[1] - 1.0f) * 0.5f;

    const float* K = camK + b * 9;
    float K00 = K[0] * cam_scale;
    float K01 = K[1] * cam_scale;
    float K02 = K[2] * cam_scale;
    float K11 = K[4] * cam_scale;
    float K12 = K[5] * cam_scale;

    const float* p = inputs + (size_t)pid * 3;
    float X = p[0];
    float Y = p[1];
    float Z = p[2] - 0.8f;

    float w = (-K00 * X - K01 * Y) / Z + K02 - hr0;
    float h = K11 * (Y / Z) + K12 - hr1;
    float wn = fminf(fmaxf(w / hr0, -1.0f), 1.0f);
    float hn = fminf(fmaxf(h / hr1, -1.0f), 1.0f);

    g_proj[pid] = make_float2(wn, hn);

    int ix = min((int)((wn + 1.0f) * (SGRID * 0.5f)), SGRID - 1);
    int iy = min((int)((hn + 1.0f) * (SGRID * 0.5f)), SGRID - 1);
    int bin = (b * SGRID + iy) * SGRID + ix;
    g_binid[pid] = bin;
    atomicAdd(&g_hist[bin], 1);
}

// ---------------------------------------------------------------------------
// Exclusive scan over NBINS (single block, 1024 threads, 32 elems/thread)
// ---------------------------------------------------------------------------
__global__ void scan_kernel() {
    __shared__ int warp_sums[32];
    int t = threadIdx.x;
    int lane = t & 31, wid = t >> 5;
    const int EPT = NBINS / 1024;
    int base = t * EPT;
    int vals[EPT];
    int s = 0;
#pragma unroll
    for (int i = 0; i < EPT; i++) { vals[i] = g_hist[base + i]; s += vals[i]; }

    int x = s;
#pragma unroll
    for (int off = 1; off < 32; off <<= 1) {
        int y = __shfl_up_sync(0xffffffffu, x, off);
        if (lane >= off) x += y;
    }
    if (lane == 31) warp_sums[wid] = x;
    __syncthreads();
    if (wid == 0) {
        int y = warp_sums[lane];
#pragma unroll
        for (int off = 1; off < 32; off <<= 1) {
            int z = __shfl_up_sync(0xffffffffu, y, off);
            if (lane >= off) y += z;
        }
        warp_sums[lane] = y;
    }
    __syncthreads();
    int excl = x - s + (wid > 0 ? warp_sums[wid - 1] : 0);
    int run = excl;
#pragma unroll
    for (int i = 0; i < EPT; i++) { g_cursor[base + i] = run; run += vals[i]; }
}

// ---------------------------------------------------------------------------
// Scatter: build permutation
// ---------------------------------------------------------------------------
__global__ void scatter_kernel() {
    int pid = blockIdx.x * blockDim.x + threadIdx.x;
    if (pid >= TOTALP) return;
    int pos = atomicAdd(&g_cursor[g_binid[pid]], 1);
    g_perm[pos] = pid;
}

// ---------------------------------------------------------------------------
// Gather helpers (fp16 NHWC)
// ---------------------------------------------------------------------------
__device__ __forceinline__ void acc4(const __half* __restrict__ p, float w,
                                     float& r0, float& r1, float& r2, float& r3) {
    uint2 v = *(const uint2*)p;
    __half2 h0 = *reinterpret_cast<const __half2*>(&v.x);
    __half2 h1 = *reinterpret_cast<const __half2*>(&v.y);
    float2 f0 = __half22float2(h0);
    float2 f1 = __half22float2(h1);
    r0 = fmaf(f0.x, w, r0);
    r1 = fmaf(f0.y, w, r1);
    r2 = fmaf(f1.x, w, r2);
    r3 = fmaf(f1.y, w, r3);
}

template <int C, int H, int W, int OFF>
__device__ __forceinline__ void sample_level(const __half* __restrict__ g,
                                             int b, int lane,
                                             float wn, float hn,
                                             float* __restrict__ orow) {
    float x = ((wn + 1.0f) * (float)W - 1.0f) * 0.5f;
    float y = ((hn + 1.0f) * (float)H - 1.0f) * 0.5f;
    float fx0 = floorf(x), fy0 = floorf(y);
    float tx = x - fx0, ty = y - fy0;
    int x0 = (int)fx0, y0 = (int)fy0;
    int x1 = x0 + 1,   y1 = y0 + 1;

    float wx0 = 1.0f - tx, wx1 = tx;
    float wy0 = 1.0f - ty, wy1 = ty;

    bool vx0 = (x0 >= 0) && (x0 < W);
    bool vx1 = (x1 >= 0) && (x1 < W);
    bool vy0 = (y0 >= 0) && (y0 < H);
    bool vy1 = (y1 >= 0) && (y1 < H);

    float w00 = (vx0 && vy0) ? wx0 * wy0 : 0.0f;
    float w10 = (vx1 && vy0) ? wx1 * wy0 : 0.0f;
    float w01 = (vx0 && vy1) ? wx0 * wy1 : 0.0f;
    float w11 = (vx1 && vy1) ? wx1 * wy1 : 0.0f;

    int x0c = min(max(x0, 0), W - 1), x1c = min(max(x1, 0), W - 1);
    int y0c = min(max(y0, 0), H - 1), y1c = min(max(y1, 0), H - 1);

    const __half* row0 = g + ((size_t)(b * H + y0c) * W) * C;
    const __half* row1 = g + ((size_t)(b * H + y1c) * W) * C;
    const __half* p00 = row0 + (size_t)x0c * C;
    const __half* p10 = row0 + (size_t)x1c * C;
    const __half* p01 = row1 + (size_t)x0c * C;
    const __half* p11 = row1 + (size_t)x1c * C;

#pragma unroll
    for (int c = lane * 4; c < C; c += 128) {
        float r0 = 0.f, r1 = 0.f, r2 = 0.f, r3 = 0.f;
        acc4(p00 + c, w00, r0, r1, r2, r3);
        acc4(p10 + c, w10, r0, r1, r2, r3);
        acc4(p01 + c, w01, r0, r1, r2, r3);
        acc4(p11 + c, w11, r0, r1, r2, r3);
        float* o = orow + OFF + c;
        o[0] = r0; o[1] = r1; o[2] = r2; o[3] = r3;
    }
}

// ---------------------------------------------------------------------------
// Main gather kernel: 1 warp per permuted point slot, 8 warps (256 thr) per
// block — same launch shape as the 256us round-2 kernel (no reg cap, no
// spills). Consecutive slots are same-bin => L1 corner-line reuse.
// ---------------------------------------------------------------------------
__global__ void gather_kernel(const float* __restrict__ inputs,
                              float* __restrict__ out) {
    int slot = (blockIdx.x * blockDim.x + threadIdx.x) >> 5;
    int lane = threadIdx.x & 31;
    if (slot >= TOTALP) return;

    int pid = g_perm[slot];
    int b = pid / NPTS;

    float2 pr = g_proj[pid];
    float wn = pr.x, hn = pr.y;

    const float* p = inputs + (size_t)pid * 3;
    float* orow = out + (size_t)pid * OUTC;
    if (lane < 3) orow[lane] = p[lane];

    sample_level<64, 128, 128, 3>(g_f0, b, lane, wn, hn, orow);
    sample_level<128, 64, 64, 67>(g_f1, b, lane, wn, hn, orow);
    sample_level<256, 32, 32, 195>(g_f2, b, lane, wn, hn, orow);
    sample_level<512, 16, 16, 451>(g_f3, b, lane, wn, hn, orow);
}

extern "C" void kernel_launch(void* const* d_in, const int* in_sizes, int n_in,
                              void* d_out, int out_size) {
    const float* resolution = (const float*)d_in[0];
    const float* feat0 = (const float*)d_in[1];
    const float* feat1 = (const float*)d_in[2];
    const float* feat2 = (const float*)d_in[3];
    const float* feat3 = (const float*)d_in[4];
    const float* inputs = (const float*)d_in[5];
    const float* camK = (const float*)d_in[6];
    float* out = (float*)d_out;

    __half *pf0, *pf1, *pf2, *pf3;
    cudaGetSymbolAddress((void**)&pf0, g_f0);
    cudaGetSymbolAddress((void**)&pf1, g_f1);
    cudaGetSymbolAddress((void**)&pf2, g_f2);
    cudaGetSymbolAddress((void**)&pf3, g_f3);
    void* phist;
    cudaGetSymbolAddress(&phist, g_hist);

    dim3 tb(32, 8);
    transpose_nchw_nhwc_h<<<dim3(128 * 128 / 32, 64 / 32, BNUM), tb>>>(feat0, pf0, 64, 128 * 128);
    transpose_nchw_nhwc_h<<<dim3(64 * 64 / 32, 128 / 32, BNUM), tb>>>(feat1, pf1, 128, 64 * 64);
    transpose_nchw_nhwc_h<<<dim3(32 * 32 / 32, 256 / 32, BNUM), tb>>>(feat2, pf2, 256, 32 * 32);
    transpose_nchw_nhwc_h<<<dim3(16 * 16 / 32, 512 / 32, BNUM), tb>>>(feat3, pf3, 512, 16 * 16);

    cudaMemsetAsync(phist, 0, NBINS * sizeof(int));
    proj_bin_kernel<<<(TOTALP + 255) / 256, 256>>>(resolution, inputs, camK);
    scan_kernel<<<1, 1024>>>();
    scatter_kernel<<<(TOTALP + 255) / 256, 256>>>();

    const int WARPS_PER_BLOCK = 8;  // 256 threads — no reg cap, no spills
    int nblocks = (TOTALP + WARPS_PER_BLOCK - 1) / WARPS_PER_BLOCK;
    gather_kernel<<<nblocks, WARPS_PER_BLOCK * 32>>>(inputs, out);
}